// round 17
// baseline (speedup 1.0000x reference)
#include <cuda_runtime.h>
#include <cstdint>

// Identity op: reference output == input X. Pure 128 MiB HBM copy.
//
// R16 = resubmission of R15 (container infra failed twice before running).
// Deep-MLP, low-occupancy sweep corner: 8 x 256-bit v8.f32 per thread
// (256 B), all loads front-batched (~80 regs -> occ ~25%, 2048 blocks).
// Same outstanding-byte depth as the converged config but fewer concurrent
// CTAs -> less cross-CTA L1tex-queue interference.
// Sweep so far: occ 41% -> 37.5us, occ 49% -> 36.7-37.6us (best),
// occ 77-82% -> 37.6-38.7us.

__device__ __forceinline__ void ldg256(const float* __restrict__ p, float* v) {
    asm volatile(
        "ld.global.nc.v8.f32 {%0,%1,%2,%3,%4,%5,%6,%7}, [%8];"
        : "=f"(v[0]), "=f"(v[1]), "=f"(v[2]), "=f"(v[3]),
          "=f"(v[4]), "=f"(v[5]), "=f"(v[6]), "=f"(v[7])
        : "l"(p));
}

__device__ __forceinline__ void stg256(float* __restrict__ p, const float* v) {
    asm volatile(
        "st.global.v8.f32 [%0], {%1,%2,%3,%4,%5,%6,%7,%8};"
        :: "l"(p),
           "f"(v[0]), "f"(v[1]), "f"(v[2]), "f"(v[3]),
           "f"(v[4]), "f"(v[5]), "f"(v[6]), "f"(v[7])
        : "memory");
}

constexpr int V8PT = 8;      // 8 x 32 B = 256 B per thread
constexpr int THREADS = 256;

__global__ void __launch_bounds__(THREADS)
copy_v8x8_kernel(const float* __restrict__ src,
                 float* __restrict__ dst,
                 long long n8) {   // count of float8 chunks
    long long base = (long long)blockIdx.x * (THREADS * V8PT) + threadIdx.x;

    float v[V8PT][8];
    // Front-batch all 8 independent 256-bit LDGs per thread.
    #pragma unroll
    for (int j = 0; j < V8PT; j++) {
        long long i = base + (long long)j * THREADS;
        if (i < n8) ldg256(src + i * 8, v[j]);
    }
    #pragma unroll
    for (int j = 0; j < V8PT; j++) {
        long long i = base + (long long)j * THREADS;
        if (i < n8) stg256(dst + i * 8, v[j]);
    }
}

// Scalar fallback for arbitrary sizes/alignment.
__global__ void copy_f1_kernel(const float* __restrict__ src,
                               float* __restrict__ dst,
                               long long n) {
    long long i = (long long)blockIdx.x * blockDim.x + threadIdx.x;
    long long stride = (long long)gridDim.x * blockDim.x;
    for (; i < n; i += stride) dst[i] = src[i];
}

extern "C" void kernel_launch(void* const* d_in, const int* in_sizes, int n_in,
                              void* d_out, int out_size) {
    const float* x = (const float*)d_in[0];
    float* out = (float*)d_out;
    long long n = (long long)out_size;   // 33,554,432 floats expected

    if ((n & 7) == 0 && (((uintptr_t)x | (uintptr_t)out) & 31) == 0) {
        long long n8 = n >> 3;
        const long long per_block = (long long)THREADS * V8PT;   // 2048 float8
        long long blocks_ll = (n8 + per_block - 1) / per_block;  // 2048 expected
        if (blocks_ll <= 1048576LL) {
            copy_v8x8_kernel<<<(int)blocks_ll, THREADS>>>(x, out, n8);
            return;
        }
    }
    int blocks = (int)(((n >> 2) + 255) / 256);
    if (blocks < 1) blocks = 1;
    if (blocks > 262144) blocks = 262144;
    copy_f1_kernel<<<blocks, 256>>>(x, out, n);
}